// round 3
// baseline (speedup 1.0000x reference)
#include <cuda_runtime.h>

// CTC batch cost, log2-domain forward algorithm.
// B=256, T=512, C=128, U=48 -> S=97 extended states. Blank = C-1 = 127.
// One CTA handles 2 batch items: threads [0,128) -> batch b0, [128,256) -> b1.
// Each thread owns one state s (s<97) and one class column for the row load.

#define Bc 256
#define Tc 512
#define Cc 128
#define Uc 48
#define Sc 97            // 2*U+1
#define BLANKC 127
#define NEGF (-1e30f)
#define EPSF 1e-7f
#define PF 8             // prefetch depth (register ring)

__device__ __forceinline__ float ex2f_(float x) {
    float y; asm("ex2.approx.f32 %0, %1;" : "=f"(y) : "f"(x)); return y;
}
__device__ __forceinline__ float lg2f_(float x) {
    float y; asm("lg2.approx.f32 %0, %1;" : "=f"(y) : "f"(x)); return y;
}

__global__ __launch_bounds__(256, 2)
void ctc_fwd_kernel(const void* __restrict__ yt_raw,
                    const float* __restrict__ y_pred,
                    float* __restrict__ out)
{
    __shared__ int   s_ext[2][Sc];
    __shared__ unsigned char s_skip[2][Sc];
    __shared__ float s_alpha[2][2][Sc + 1];   // [batch-in-block][buffer][state]
    __shared__ float s_row[2][2][Cc];         // [batch-in-block][buffer][class] log2-probs
    __shared__ int   s_is64;

    const int tid  = threadIdx.x;
    const int lb   = tid >> 7;       // 0/1: which batch item in this block
    const int ltid = tid & 127;      // lane within the batch sub-block
    const int b    = blockIdx.x * 2 + lb;

    // ---- label dtype detection (int32 vs int64), deterministic ----
    if (tid == 0) s_is64 = 1;
    __syncthreads();
    {
        const long long* p64 = (const long long*)yt_raw;   // 512B probe, safe in both layouts
        for (int i = tid; i < 64; i += 256) {
            long long v = p64[i];
            if (v < 0 || v > 127) atomicAnd(&s_is64, 0);
        }
    }
    __syncthreads();
    const bool is64 = (s_is64 != 0);

    // ---- build extended label sequence + skip mask ----
    const int*       p32 = (const int*)yt_raw;
    const long long* p64 = (const long long*)yt_raw;
    if (ltid < Sc) {
        int lab;
        if (ltid & 1) {
            int u = ltid >> 1;
            lab = is64 ? (int)p64[b * Uc + u] : p32[b * Uc + u];
        } else {
            lab = BLANKC;
        }
        s_ext[lb][ltid] = lab;
    }
    __syncthreads();
    bool mysk = false;
    int  myext = 0;
    if (ltid < Sc) {
        int e = s_ext[lb][ltid];
        bool ok = (e != BLANKC) && ((ltid < 2) ? true : (e != s_ext[lb][ltid - 2]));
        s_skip[lb][ltid] = ok ? 1 : 0;
        mysk = ok;
        myext = e;
    }

    // ---- t = 0: load row, init alpha ----
    const float* gp = y_pred + (size_t)b * Tc * Cc + ltid;  // this thread's class column
    float p0 = gp[0];
    s_row[lb][0][ltid] = lg2f_(p0 + EPSF);
    __syncthreads();
    if (ltid < Sc) {
        s_alpha[lb][0][ltid] = (ltid < 2) ? s_row[lb][0][myext] : NEGF;
    }

    // ---- prefetch rows 1..PF into a register ring ----
    float pbuf[PF];
#pragma unroll
    for (int j = 0; j < PF; j++) pbuf[j] = gp[(size_t)(1 + j) * Cc];

    // ---- main recursion: 1 __syncthreads per timestep, double-buffered smem ----
    for (int t0 = 1; t0 < Tc; t0 += PF) {
#pragma unroll
        for (int j = 0; j < PF; j++) {
            const int t = t0 + j;
            if (t < Tc) {
                const int cur = t & 1;
                const int prv = cur ^ 1;
                float l2 = lg2f_(pbuf[j] + EPSF);
                if (t + PF < Tc) pbuf[j] = gp[(size_t)(t + PF) * Cc];  // refill ring
                s_row[lb][cur][ltid] = l2;
                __syncthreads();
                if (ltid < Sc) {
                    float a  = s_alpha[lb][prv][ltid];
                    float a1 = (ltid >= 1) ? s_alpha[lb][prv][ltid - 1] : NEGF;
                    float a2 = (ltid >= 2 && mysk) ? s_alpha[lb][prv][ltid - 2] : NEGF;
                    float m  = fmaxf(a, fmaxf(a1, a2));
                    float sum = ex2f_(a - m) + ex2f_(a1 - m) + ex2f_(a2 - m);
                    s_alpha[lb][cur][ltid] = m + lg2f_(sum) + s_row[lb][cur][myext];
                }
            }
        }
    }

    __syncthreads();
    if (ltid == 0) {
        const int lastbuf = (Tc - 1) & 1;
        float x = s_alpha[lb][lastbuf][Sc - 1];
        float y = s_alpha[lb][lastbuf][Sc - 2];
        float m = fmaxf(x, y);
        float ll2 = m + lg2f_(ex2f_(x - m) + ex2f_(y - m));
        out[b] = -ll2 * 0.69314718055994530942f;   // log2 -> natural log
    }
}

extern "C" void kernel_launch(void* const* d_in, const int* in_sizes, int n_in,
                              void* d_out, int out_size)
{
    (void)in_sizes; (void)n_in; (void)out_size;
    const void*  y_true = d_in[0];
    const float* y_pred = (const float*)d_in[1];
    float* out = (float*)d_out;
    ctc_fwd_kernel<<<Bc / 2, 256>>>(y_true, y_pred, out);
}

// round 4
// speedup vs baseline: 1.0097x; 1.0097x over previous
#include <cuda_runtime.h>

// CTC batch cost, log2-domain forward algorithm.
// B=256, T=512, C=128, U=48 -> S=97 extended states. Blank = C-1 = 127.
// One CTA handles 2 batch items: threads [0,128) -> batch b0, [128,256) -> b1.
// Each thread owns one state s (s<97) and one class column for the row load.

#define Bc 256
#define Tc 512
#define Cc 128
#define Uc 48
#define Sc 97            // 2*U+1
#define BLANKC 127
#define NEGF (-1e30f)
#define EPSF 1e-7f
#define PF 8             // prefetch depth (register ring)

__device__ __forceinline__ float ex2f_(float x) {
    float y; asm("ex2.approx.f32 %0, %1;" : "=f"(y) : "f"(x)); return y;
}
__device__ __forceinline__ float lg2f_(float x) {
    float y; asm("lg2.approx.f32 %0, %1;" : "=f"(y) : "f"(x)); return y;
}

__global__ __launch_bounds__(256, 2)
void ctc_fwd_kernel(const void* __restrict__ yt_raw,
                    const float* __restrict__ y_pred,
                    float* __restrict__ out)
{
    __shared__ int   s_ext[2][Sc];
    __shared__ unsigned char s_skip[2][Sc];
    __shared__ float s_alpha[2][2][Sc + 1];   // [batch-in-block][buffer][state]
    __shared__ float s_row[2][2][Cc];         // [batch-in-block][buffer][class] log2-probs
    __shared__ int   s_is64;

    const int tid  = threadIdx.x;
    const int lb   = tid >> 7;       // 0/1: which batch item in this block
    const int ltid = tid & 127;      // lane within the batch sub-block
    const int b    = blockIdx.x * 2 + lb;

    // ---- label dtype detection (int32 vs int64), deterministic ----
    if (tid == 0) s_is64 = 1;
    __syncthreads();
    {
        const long long* p64 = (const long long*)yt_raw;   // 512B probe, safe in both layouts
        for (int i = tid; i < 64; i += 256) {
            long long v = p64[i];
            if (v < 0 || v > 127) atomicAnd(&s_is64, 0);
        }
    }
    __syncthreads();
    const bool is64 = (s_is64 != 0);

    // ---- build extended label sequence + skip mask ----
    const int*       p32 = (const int*)yt_raw;
    const long long* p64 = (const long long*)yt_raw;
    if (ltid < Sc) {
        int lab;
        if (ltid & 1) {
            int u = ltid >> 1;
            lab = is64 ? (int)p64[b * Uc + u] : p32[b * Uc + u];
        } else {
            lab = BLANKC;
        }
        s_ext[lb][ltid] = lab;
    }
    __syncthreads();
    bool mysk = false;
    int  myext = 0;
    if (ltid < Sc) {
        int e = s_ext[lb][ltid];
        bool ok = (e != BLANKC) && ((ltid < 2) ? true : (e != s_ext[lb][ltid - 2]));
        s_skip[lb][ltid] = ok ? 1 : 0;
        mysk = ok;
        myext = e;
    }

    // ---- t = 0: load row, init alpha ----
    const float* gp = y_pred + (size_t)b * Tc * Cc + ltid;  // this thread's class column
    float p0 = gp[0];
    s_row[lb][0][ltid] = lg2f_(p0 + EPSF);
    __syncthreads();
    if (ltid < Sc) {
        s_alpha[lb][0][ltid] = (ltid < 2) ? s_row[lb][0][myext] : NEGF;
    }

    // ---- prefetch rows 1..PF into a register ring ----
    float pbuf[PF];
#pragma unroll
    for (int j = 0; j < PF; j++) pbuf[j] = gp[(size_t)(1 + j) * Cc];

    // ---- main recursion: 1 __syncthreads per timestep, double-buffered smem ----
    for (int t0 = 1; t0 < Tc; t0 += PF) {
#pragma unroll
        for (int j = 0; j < PF; j++) {
            const int t = t0 + j;
            if (t < Tc) {
                const int cur = t & 1;
                const int prv = cur ^ 1;
                float l2 = lg2f_(pbuf[j] + EPSF);
                if (t + PF < Tc) pbuf[j] = gp[(size_t)(t + PF) * Cc];  // refill ring
                s_row[lb][cur][ltid] = l2;
                __syncthreads();
                if (ltid < Sc) {
                    float a  = s_alpha[lb][prv][ltid];
                    float a1 = (ltid >= 1) ? s_alpha[lb][prv][ltid - 1] : NEGF;
                    float a2 = (ltid >= 2 && mysk) ? s_alpha[lb][prv][ltid - 2] : NEGF;
                    float m  = fmaxf(a, fmaxf(a1, a2));
                    float sum = ex2f_(a - m) + ex2f_(a1 - m) + ex2f_(a2 - m);
                    s_alpha[lb][cur][ltid] = m + lg2f_(sum) + s_row[lb][cur][myext];
                }
            }
        }
    }

    __syncthreads();
    if (ltid == 0) {
        const int lastbuf = (Tc - 1) & 1;
        float x = s_alpha[lb][lastbuf][Sc - 1];
        float y = s_alpha[lb][lastbuf][Sc - 2];
        float m = fmaxf(x, y);
        float ll2 = m + lg2f_(ex2f_(x - m) + ex2f_(y - m));
        out[b] = -ll2 * 0.69314718055994530942f;   // log2 -> natural log
    }
}

extern "C" void kernel_launch(void* const* d_in, const int* in_sizes, int n_in,
                              void* d_out, int out_size)
{
    (void)in_sizes; (void)n_in; (void)out_size;
    const void*  y_true = d_in[0];
    const float* y_pred = (const float*)d_in[1];
    float* out = (float*)d_out;
    ctc_fwd_kernel<<<Bc / 2, 256>>>(y_true, y_pred, out);
}

// round 8
// speedup vs baseline: 4.2969x; 4.2555x over previous
#include <cuda_runtime.h>

// CTC batch cost, linear-domain forward with PER-LANE exact power-of-2
// renormalization + coalesced cp.async row staging.
// B=256, T=512, C=128, U=48 -> S=97 states. Blank = 127.
// One warp per batch item; lane l owns states 4l..4l+3. Cross-lane coupling:
// one shfl of a3 per step, rescaled by exact 2^(eacc_left - eacc).

#define Bc 256
#define Tc 512
#define Cc 128
#define Uc 48
#define BLANKC 127
#define EPSF 1e-7f
#define FULLM 0xffffffffu

__device__ __forceinline__ float lg2f_(float x) {
    float y; asm("lg2.approx.f32 %0, %1;" : "=f"(y) : "f"(x)); return y;
}
__device__ __forceinline__ unsigned smem_u32(const void* p) {
    unsigned a;
    asm("{ .reg .u64 t; cvta.to.shared.u64 t, %1; cvt.u32.u64 %0, t; }"
        : "=r"(a) : "l"(p));
    return a;
}
__device__ __forceinline__ void cpa16(unsigned dst, const void* src) {
    asm volatile("cp.async.cg.shared.global [%0], [%1], 16;"
                 :: "r"(dst), "l"(src) : "memory");
}
__device__ __forceinline__ void cpcommit() {
    asm volatile("cp.async.commit_group;" ::: "memory");
}
__device__ __forceinline__ void cpwait1() {
    asm volatile("cp.async.wait_group 1;" ::: "memory");
}

__global__ __launch_bounds__(64)
void ctc_lin2_kernel(const void* __restrict__ yt_raw,
                     const float* __restrict__ y_pred,
                     float* __restrict__ out)
{
    // 16B alignment REQUIRED for cp.async.cg 16-byte stores.
    __shared__ __align__(128) float rows[2][2][8][Cc];  // [warp][buf][slot][class]

    const int tid  = threadIdx.x;
    const int lane = tid & 31;
    const int w    = tid >> 5;
    const int b    = blockIdx.x * 2 + w;

    // ---- label dtype probe (int64 vs int32), deterministic ----
    const long long* q64 = (const long long*)yt_raw;
    long long v0 = q64[lane * 2], v1 = q64[lane * 2 + 1];
    bool inr = (v0 >= 0 && v0 <= 127 && v1 >= 0 && v1 <= 127);
    bool is64 = __all_sync(FULLM, inr);
    const int* q32 = (const int*)yt_raw;

    // ---- per-lane labels + skip flags ----
    int u0 = 2 * lane, u1 = 2 * lane + 1;
    int cu0 = (u0 < Uc) ? u0 : 0;
    int cu1 = (u1 < Uc) ? u1 : 0;
    int l0 = is64 ? (int)q64[b * Uc + cu0] : q32[b * Uc + cu0];
    int l1 = is64 ? (int)q64[b * Uc + cu1] : q32[b * Uc + cu1];
    int lprev = __shfl_up_sync(FULLM, l1, 1);
    float sk1 = (u0 == 0 || l0 != lprev) ? 1.f : 0.f;
    float sk3 = (l1 != l0) ? 1.f : 0.f;

    const float* base = y_pred + (size_t)b * Tc * Cc;

    // ---- t = 0 init ----
    float a0 = (lane == 0) ? base[BLANKC] + EPSF : 0.f;
    float a1 = (lane == 0) ? base[l0] + EPSF : 0.f;
    float a2 = 0.f, a3 = 0.f;
    int   eacc = 0;
    float scL  = (lane == 0) ? 0.f : 1.f;   // 2^(eaccL - eacc), exact

    // ---- prefill periods 0 and 1 (rows t=1..8, 9..16) ----
    unsigned sb = smem_u32(&rows[w][0][0][0]);
    for (int p = 0; p < 2; p++) {
        for (int j = 0; j < 8; j++) {
            int t = 1 + 8 * p + j;
            unsigned dst = sb + (unsigned)((p * 8 + j) * Cc * 4 + lane * 16);
            cpa16(dst, base + (size_t)t * Cc + lane * 4);
        }
        cpcommit();
    }

    // ---- main loop: periods k=0..62 cover t = 1..504 ----
    for (int k = 0; k < 63; k++) {
        cpwait1();
        __syncwarp();
        const float* bufp = &rows[w][k & 1][0][0];

#pragma unroll
        for (int j = 0; j < 8; j++) {
            const float* r = bufp + j * Cc;
            float pb  = r[BLANKC] + EPSF;
            float pl0 = r[l0] + EPSF;
            float pl1 = r[l1] + EPSF;
            float pa3 = __shfl_up_sync(FULLM, a3, 1) * scL;  // exact rescale
            float n0 = (a0 + pa3) * pb;
            float n1 = fmaf(sk1, pa3, a0 + a1) * pl0;
            float n2 = (a1 + a2) * pb;
            float n3 = fmaf(sk3, a1, a2 + a3) * pl1;
            a0 = n0; a1 = n1; a2 = n2; a3 = n3;
        }
        __syncwarp();

        // prefetch period k+2 into the buffer just consumed
        if (k + 2 <= 63) {
            for (int j = 0; j < 8; j++) {
                int t = 1 + 8 * (k + 2) + j;
                if (t > Tc - 1) t = Tc - 1;           // clamp (slot unused)
                unsigned dst = sb + (unsigned)(((k & 1) * 8 + j) * Cc * 4 + lane * 16);
                cpa16(dst, base + (size_t)t * Cc + lane * 4);
            }
        }
        cpcommit();   // always one group per iteration (possibly empty)

        // ---- per-lane renorm (error-free power-of-2 scaling) ----
        float m = fmaxf(fmaxf(a0, a1), fmaxf(a2, a3));
        bool alive = (m > 0.f);
        int e = ((__float_as_int(m) >> 23) & 0xff) - 167;    // unbiased exp - 40
        e = e < -126 ? -126 : (e > 126 ? 126 : e);
        int cand = eacc + (alive ? e : 0);
        int adopt = __reduce_min_sync(FULLM, alive ? cand : 0x7fffffff);
        if (alive) {
            float sc = __int_as_float((unsigned)(127 - e) << 23);  // 2^-e exact
            a0 *= sc; a1 *= sc; a2 *= sc; a3 *= sc;
            eacc = cand;
        } else {
            eacc = adopt;   // all dead lanes share the global frontier scale
        }
        int eL = __shfl_up_sync(FULLM, eacc, 1);   // POST-adopt: dead->dead scL=1
        int de = eL - eacc;
        int dc = de > 126 ? 126 : de;
        scL = (lane == 0 || de < -126)
                ? 0.f
                : __int_as_float((unsigned)(127 + dc) << 23);       // 2^de exact
    }

    // ---- epilogue: period 63, t = 505..511 (7 steps) ----
    {
        cpwait1();
        __syncwarp();
        const float* bufp = &rows[w][1][0][0];
#pragma unroll
        for (int j = 0; j < 7; j++) {
            const float* r = bufp + j * Cc;
            float pb  = r[BLANKC] + EPSF;
            float pl0 = r[l0] + EPSF;
            float pl1 = r[l1] + EPSF;
            float pa3 = __shfl_up_sync(FULLM, a3, 1) * scL;
            float n0 = (a0 + pa3) * pb;
            float n1 = fmaf(sk1, pa3, a0 + a1) * pl0;
            float n2 = (a1 + a2) * pb;
            float n3 = fmaf(sk3, a1, a2 + a3) * pl1;
            a0 = n0; a1 = n1; a2 = n2; a3 = n3;
        }
    }

    // ---- finish: true values v·2^eacc; states 95 (lane23,a3), 96 (lane24,a0)
    float v95 = __shfl_sync(FULLM, a3, 23); int e95 = __shfl_sync(FULLM, eacc, 23);
    float v96 = __shfl_sync(FULLM, a0, 24); int e96 = __shfl_sync(FULLM, eacc, 24);
    if (lane == 0) {
        int em = e95 > e96 ? e95 : e96;
        float s = ldexpf(v95, e95 - em) + ldexpf(v96, e96 - em);
        float ll2 = lg2f_(s) + (float)em;                 // total log2-prob
        out[b] = -ll2 * 0.69314718055994530942f;          // -> -ln prob
    }
}

extern "C" void kernel_launch(void* const* d_in, const int* in_sizes, int n_in,
                              void* d_out, int out_size)
{
    (void)in_sizes; (void)n_in; (void)out_size;
    const void*  y_true = d_in[0];
    const float* y_pred = (const float*)d_in[1];
    float* out = (float*)d_out;
    ctc_lin2_kernel<<<Bc / 2, 64>>>(y_true, y_pred, out);
}

// round 9
// speedup vs baseline: 4.8403x; 1.1265x over previous
#include <cuda_runtime.h>

// CTC batch cost, linear-domain forward. v3: pipelined shfl, off-chain renorm
// (stale decision @ step 5, bias 2^80), 4-deep cp.async pipeline, register
// pre-gather of row probs, eps folded out (error ~1e-5 << 1e-3 tol).
// One warp per batch item; lane l owns states 4l..4l+3.

#define Bc 256
#define Tc 512
#define Cc 128
#define Uc 48
#define BLANKC 127
#define FULLM 0xffffffffu
#define EBIAS 207          // 127 + 80: renorm target exponent 2^80

__device__ __forceinline__ float lg2f_(float x) {
    float y; asm("lg2.approx.f32 %0, %1;" : "=f"(y) : "f"(x)); return y;
}
__device__ __forceinline__ unsigned smem_u32(const void* p) {
    unsigned a;
    asm("{ .reg .u64 t; cvta.to.shared.u64 t, %1; cvt.u32.u64 %0, t; }"
        : "=r"(a) : "l"(p));
    return a;
}
__device__ __forceinline__ void cpa16(unsigned dst, const void* src) {
    asm volatile("cp.async.cg.shared.global [%0], [%1], 16;"
                 :: "r"(dst), "l"(src) : "memory");
}
__device__ __forceinline__ void cpcommit() {
    asm volatile("cp.async.commit_group;" ::: "memory");
}
__device__ __forceinline__ void cpwait2() {
    asm volatile("cp.async.wait_group 2;" ::: "memory");
}
__device__ __forceinline__ void cpwait3() {
    asm volatile("cp.async.wait_group 3;" ::: "memory");
}
__device__ __forceinline__ int iclamp(int v, int lo, int hi) {
    return v < lo ? lo : (v > hi ? hi : v);
}
__device__ __forceinline__ float p2f(int e) {      // exact 2^e, e in [-126,126]
    return __int_as_float((unsigned)(127 + e) << 23);
}

// One timestep. Consumes pa3 (prev step's shfl), issues next shfl early.
#define STEP(J, SCL_, SK1S_) do {                                            \
    float a01 = a0 + a1;                                                     \
    float a23 = a2 + a3;                                                     \
    float a12 = a1 + a2;                                                     \
    float n3 = fmaf(sk3, a1, a23) * P1[J];                                   \
    float pa3n = __shfl_up_sync(FULLM, n3, 1);                               \
    float n2 = a12 * Pb[J];                                                  \
    float n1 = fmaf((SK1S_), pa3, a01) * P0[J];                              \
    float n0 = fmaf((SCL_), pa3, a0) * Pb[J];                                \
    a0 = n0; a1 = n1; a2 = n2; a3 = n3; pa3 = pa3n;                          \
} while (0)

__global__ __launch_bounds__(64)
void ctc_lin3_kernel(const void* __restrict__ yt_raw,
                     const float* __restrict__ y_pred,
                     float* __restrict__ out)
{
    __shared__ __align__(128) float rows[2][4][8][Cc];  // [warp][buf][slot][class]

    const int lane = threadIdx.x & 31;
    const int w    = threadIdx.x >> 5;
    const int b    = blockIdx.x * 2 + w;

    // ---- label dtype probe (int64 vs int32), deterministic ----
    const long long* q64 = (const long long*)yt_raw;
    long long v0 = q64[lane * 2], v1 = q64[lane * 2 + 1];
    bool inr = (v0 >= 0 && v0 <= 127 && v1 >= 0 && v1 <= 127);
    bool is64 = __all_sync(FULLM, inr);
    const int* q32 = (const int*)yt_raw;

    // ---- per-lane labels + skip flags ----
    int u0 = 2 * lane, u1 = 2 * lane + 1;
    int cu0 = (u0 < Uc) ? u0 : 0;
    int cu1 = (u1 < Uc) ? u1 : 0;
    int l0 = is64 ? (int)q64[b * Uc + cu0] : q32[b * Uc + cu0];
    int l1 = is64 ? (int)q64[b * Uc + cu1] : q32[b * Uc + cu1];
    int lprev = __shfl_up_sync(FULLM, l1, 1);
    float sk1 = (u0 == 0 || l0 != lprev) ? 1.f : 0.f;
    float sk3 = (l1 != l0) ? 1.f : 0.f;

    const float* base = y_pred + (size_t)b * Tc * Cc;
    const unsigned sbw = smem_u32(&rows[w][0][0][0]);

    // ---- t = 0 init ----
    float a0 = (lane == 0) ? base[BLANKC] : 0.f;
    float a1 = (lane == 0) ? base[l0] : 0.f;
    float a2 = 0.f, a3 = 0.f, pa3 = 0.f;
    int   eacc = 0;
    float scL  = (lane == 0) ? 0.f : 1.f;
    float scL0 = scL;
    float sk1s = sk1 * scL, sk1s0 = sk1s;

    // ---- prefill buffers for periods 0..3 (rows t = 1..32) ----
    for (int p = 0; p < 4; p++) {
        for (int j = 0; j < 8; j++) {
            int t = 1 + 8 * p + j;
            cpa16(sbw + (unsigned)(((p * 8 + j) * Cc) * 4 + lane * 16),
                  base + (size_t)t * Cc + lane * 4);
        }
        cpcommit();
    }
    cpwait3();          // period 0 resident
    __syncwarp();

    // ---- pre-gather period 0 probs into registers ----
    float Pb[8], P0[8], P1[8];
    {
        const float* r = &rows[w][0][0][0];
#pragma unroll
        for (int j = 0; j < 8; j++) {
            Pb[j] = r[j * Cc + BLANKC];
            P0[j] = r[j * Cc + l0];
            P1[j] = r[j * Cc + l1];
        }
    }

    // pending renorm state (computed @ j==5, applied after j==7)
    float sc_p = 1.f, scLn = scL, scL0n = scL;
    int   eacc_p = 0;

    // ---- main loop: periods k = 0..62 (t = 1..504) ----
    for (int k = 0; k < 63; k++) {
        cpwait2();      // buffers for periods k and k+1 resident
        __syncwarp();
        const bool pref = (k + 4 <= 63);
        const unsigned dstb = sbw + (unsigned)((k & 3) * 8 * Cc * 4 + lane * 16);

#pragma unroll
        for (int j = 0; j < 8; j++) {
            if (j == 0) STEP(0, scL0, sk1s0); else STEP(j, scL, sk1s);

            if (pref) {                       // refill this period's buffer
                int t = 8 * (k + 4) + 1 + j;
                if (t > Tc - 1) t = Tc - 1;
                cpa16(dstb + (unsigned)(j * Cc * 4),
                      base + (size_t)t * Cc + lane * 4);
            }

            if (j == 5) {                     // off-chain renorm decision
                float m5 = fmaxf(fmaxf(a0, a1), fmaxf(a2, a3));
                bool alive = (m5 > 0.f);
                int e = ((__float_as_int(m5) >> 23) & 0xff) - EBIAS;
                e = iclamp(e, -126, 126);
                int cand = eacc + e;
                int adopt = __reduce_min_sync(FULLM, alive ? cand : 0x7fffffff);
                int eaccN = alive ? cand : adopt;
                int dsc = alive ? -e : (eacc - adopt);
                sc_p = p2f(iclamp(dsc, -126, 126));
                int eLold = __shfl_up_sync(FULLM, eacc, 1);
                int eLnew = __shfl_up_sync(FULLM, eaccN, 1);
                int de0 = eLold - eaccN;
                int de  = eLnew - eaccN;
                scL0n = (lane == 0 || de0 < -126) ? 0.f : p2f(iclamp(de0, -126, 126));
                scLn  = (lane == 0 || de  < -126) ? 0.f : p2f(iclamp(de,  -126, 126));
                eacc_p = eaccN;
            }
        }
        cpcommit();                            // one group per period (may be empty)

        // ---- apply pending renorm (exact power-of-2, error-free) ----
        a0 *= sc_p; a1 *= sc_p; a2 *= sc_p; a3 *= sc_p;
        eacc = eacc_p;
        scL = scLn; scL0 = scL0n;
        sk1s = sk1 * scL; sk1s0 = sk1 * scL0;

        // ---- pre-gather period k+1 probs (buffer resident per cpwait2) ----
        {
            const float* r = &rows[w][(k + 1) & 3][0][0];
#pragma unroll
            for (int j = 0; j < 8; j++) {
                Pb[j] = r[j * Cc + BLANKC];
                P0[j] = r[j * Cc + l0];
                P1[j] = r[j * Cc + l1];
            }
        }
    }

    // ---- epilogue: period 63, t = 505..511 (7 steps), no renorm ----
#pragma unroll
    for (int j = 0; j < 7; j++) {
        if (j == 0) STEP(0, scL0, sk1s0); else STEP(j, scL, sk1s);
    }

    // ---- finish: true = stored * 2^eacc; states 95 (lane23,a3), 96 (lane24,a0)
    float v95 = __shfl_sync(FULLM, a3, 23); int e95 = __shfl_sync(FULLM, eacc, 23);
    float v96 = __shfl_sync(FULLM, a0, 24); int e96 = __shfl_sync(FULLM, eacc, 24);
    if (lane == 0) {
        int em = e95 > e96 ? e95 : e96;
        float s = ldexpf(v95, e95 - em) + ldexpf(v96, e96 - em);
        float ll2 = lg2f_(s) + (float)em;
        out[b] = -ll2 * 0.69314718055994530942f;
    }
}

extern "C" void kernel_launch(void* const* d_in, const int* in_sizes, int n_in,
                              void* d_out, int out_size)
{
    (void)in_sizes; (void)n_in; (void)out_size;
    const void*  y_true = d_in[0];
    const float* y_pred = (const float*)d_in[1];
    float* out = (float*)d_out;
    ctc_lin3_kernel<<<Bc / 2, 64>>>(y_true, y_pred, out);
}